// round 8
// baseline (speedup 1.0000x reference)
#include <cuda_runtime.h>
#include <cuda_bf16.h>

// ---------------------------------------------------------------------------
// SCN: per rank r with L (N x N), x (N x 64), W (2 x 64 x 64):
//   dinv_i = rsqrt(sum_j |L_ij|)  (0 if sum==0)
//   layer:  x = relu( dinv_i * sum_j L_ij * (dinv_j * (x @ W[layer])_j) )
//   pooled[b] = sum_{i: bel_i==b} x_i   (B=64);  out += pooled @ Wr + br
// L @ U on tensor cores (mma.sync tf32, cvt.rna fragment rounding),
// 4-stage BK=32 cp.async pipeline, fused combine+xw, 3 streams.
// ---------------------------------------------------------------------------

#define NMAX   8192
#define CCH    64
#define BSEG   64
#define OUTC   32
#define SPLIT_ELEMS 2097152            // S*N*64: 4*8192*64 == 8*4096*64

__device__ float g_dinv[3 * NMAX];
__device__ float g_u[3][NMAX * CCH];
__device__ float g_x[3][NMAX * CCH];
__device__ float g_part[3][SPLIT_ELEMS];     // per-rank split-K scratch
__device__ float g_pp[3 * 32 * BSEG * CCH];
__device__ float g_pool[3 * BSEG * CCH];

// ---------------- rowsum -> dinv ----------------
__global__ void scn_rowsum(const float* __restrict__ L, float* __restrict__ dinv, int N) {
    int row = blockIdx.x;
    const float4* Lr = (const float4*)(L + (long)row * N);
    int n4 = N >> 2;
    float s = 0.f;
    for (int j = threadIdx.x; j < n4; j += blockDim.x) {
        float4 v = Lr[j];
        s += fabsf(v.x) + fabsf(v.y) + fabsf(v.z) + fabsf(v.w);
    }
#pragma unroll
    for (int o = 16; o > 0; o >>= 1) s += __shfl_down_sync(0xffffffffu, s, o);
    __shared__ float red[8];
    int lane = threadIdx.x & 31, w = threadIdx.x >> 5;
    if (lane == 0) red[w] = s;
    __syncthreads();
    if (threadIdx.x < 8) {
        s = red[threadIdx.x];
#pragma unroll
        for (int o = 4; o > 0; o >>= 1) s += __shfl_down_sync(0xffu, s, o);
        if (threadIdx.x == 0) dinv[row] = (s > 0.f) ? rsqrtf(s) : 0.f;
    }
}

// ---------------- u = dinv .* (x @ W)  (first layer, x from input) ---------
__global__ void scn_xw(const float* __restrict__ X, const float* __restrict__ W,
                       const float* __restrict__ dinv, float* __restrict__ U, int N) {
    __shared__ float Ws[64][64];
    __shared__ float Xs[32][64];
    int t = threadIdx.x;
    int r0 = blockIdx.x * 32;
#pragma unroll
    for (int j = 0; j < 4; j++)
        ((float4*)Ws)[t + 256 * j] = ((const float4*)W)[t + 256 * j];
#pragma unroll
    for (int j = 0; j < 2; j++)
        ((float4*)Xs)[t + 256 * j] = ((const float4*)(X + (long)r0 * 64))[t + 256 * j];
    __syncthreads();
    int c = t & 63, g = t >> 6;
    float acc[8] = {0.f, 0.f, 0.f, 0.f, 0.f, 0.f, 0.f, 0.f};
#pragma unroll 16
    for (int k = 0; k < 64; k++) {
        float w = Ws[k][c];
#pragma unroll
        for (int r = 0; r < 8; r++)
            acc[r] = fmaf(Xs[g * 8 + r][k], w, acc[r]);
    }
#pragma unroll
    for (int r = 0; r < 8; r++) {
        int row = r0 + g * 8 + r;
        U[(long)row * 64 + c] = dinv[row] * acc[r];
    }
}

// ---------------- tf32 split-K GEMM, 4-stage BK=32 cp.async ----------------
#define LS_STRIDE 36
#define US_STRIDE 68
#define LS_SZ (128 * LS_STRIDE)
#define US_SZ (32 * US_STRIDE)
#define STAGES 4
#define GEMM_SMEM ((STAGES * (LS_SZ + US_SZ)) * 4)

__device__ __forceinline__ void cpa16(unsigned smaddr, const void* g) {
    asm volatile("cp.async.cg.shared.global [%0], [%1], 16;" :: "r"(smaddr), "l"(g));
}
__device__ __forceinline__ unsigned rna(unsigned x) {
    unsigned r;
    asm("cvt.rna.tf32.f32 %0, %1;" : "=r"(r) : "r"(x));
    return r;
}

__global__ __launch_bounds__(256, 2)
void scn_gemm_tf32(const float* __restrict__ L, const float* __restrict__ U,
                   float* __restrict__ P, int N, int kChunk) {
    extern __shared__ float smem[];
    unsigned sbase = (unsigned)__cvta_generic_to_shared(smem);
    const unsigned* SU = (const unsigned*)smem;
    unsigned ls_addr = sbase;
    unsigned us_addr = sbase + (unsigned)STAGES * LS_SZ * 4u;
    const int us_off = STAGES * LS_SZ;

    int t = threadIdx.x;
    int wid = t >> 5, lane = t & 31;
    int g = lane >> 2, tq = lane & 3;
    int warp_m = wid & 3, warp_n = wid >> 2;          // 4 x 2 warp grid
    int m0 = blockIdx.x * 128;
    long kbase = (long)blockIdx.y * kChunk;
    int iters = kChunk / 32;

    // cp.async thread slots: L 128x32 (1024 float4), U 32x64 (512 float4)
    int l_row[4], l_c4[4], u_row[2], u_c4[2];
#pragma unroll
    for (int j = 0; j < 4; j++) { int f = t + 256 * j; l_row[j] = f >> 3; l_c4[j] = f & 7; }
#pragma unroll
    for (int j = 0; j < 2; j++) { int f = t + 256 * j; u_row[j] = f >> 4; u_c4[j] = f & 15; }

    float acc[2][4][4];
#pragma unroll
    for (int mi = 0; mi < 2; mi++)
#pragma unroll
        for (int ni = 0; ni < 4; ni++)
#pragma unroll
            for (int q = 0; q < 4; q++) acc[mi][ni][q] = 0.f;

#define ISSUE_TILE(IT, BUF)                                                              \
    do {                                                                                 \
        long k0_ = kbase + (long)(IT) * 32;                                              \
        _Pragma("unroll")                                                                \
        for (int j = 0; j < 4; j++)                                                      \
            cpa16(ls_addr + ((BUF) * LS_SZ + l_row[j] * LS_STRIDE + l_c4[j] * 4) * 4u,   \
                  L + (long)(m0 + l_row[j]) * N + k0_ + l_c4[j] * 4);                    \
        _Pragma("unroll")                                                                \
        for (int j = 0; j < 2; j++)                                                      \
            cpa16(us_addr + ((BUF) * US_SZ + u_row[j] * US_STRIDE + u_c4[j] * 4) * 4u,   \
                  U + (k0_ + u_row[j]) * 64 + u_c4[j] * 4);                              \
        asm volatile("cp.async.commit_group;");                                          \
    } while (0)

    // prologue: issue 3 tiles ahead (iters >= 16 always)
    ISSUE_TILE(0, 0);
    ISSUE_TILE(1, 1);
    ISSUE_TILE(2, 2);

    for (int it = 0; it < iters; it++) {
        int buf = it & (STAGES - 1);
        if (it + 3 < iters) {
            ISSUE_TILE(it + 3, (it + 3) & (STAGES - 1));
            asm volatile("cp.async.wait_group 3;");
        } else {
            int rem = iters - 1 - it;        // groups allowed to stay pending
            if (rem == 2)      asm volatile("cp.async.wait_group 2;");
            else if (rem == 1) asm volatile("cp.async.wait_group 1;");
            else               asm volatile("cp.async.wait_group 0;");
        }
        __syncthreads();

        const unsigned* Lb = SU + buf * LS_SZ;
        const unsigned* Ub = SU + us_off + buf * US_SZ;
#pragma unroll
        for (int kk = 0; kk < 4; kk++) {
            int k = kk * 8;
            unsigned a[2][4], b[4][2];
#pragma unroll
            for (int mi = 0; mi < 2; mi++) {
                int r = warp_m * 32 + mi * 16 + g;
                a[mi][0] = rna(Lb[r * LS_STRIDE + k + tq]);
                a[mi][1] = rna(Lb[(r + 8) * LS_STRIDE + k + tq]);
                a[mi][2] = rna(Lb[r * LS_STRIDE + k + tq + 4]);
                a[mi][3] = rna(Lb[(r + 8) * LS_STRIDE + k + tq + 4]);
            }
#pragma unroll
            for (int ni = 0; ni < 4; ni++) {
                int c = warp_n * 32 + ni * 8 + g;
                b[ni][0] = rna(Ub[(k + tq) * US_STRIDE + c]);
                b[ni][1] = rna(Ub[(k + tq + 4) * US_STRIDE + c]);
            }
#pragma unroll
            for (int mi = 0; mi < 2; mi++)
#pragma unroll
                for (int ni = 0; ni < 4; ni++)
                    asm volatile(
                        "mma.sync.aligned.m16n8k8.row.col.f32.tf32.tf32.f32 "
                        "{%0,%1,%2,%3}, {%4,%5,%6,%7}, {%8,%9}, {%0,%1,%2,%3};"
                        : "+f"(acc[mi][ni][0]), "+f"(acc[mi][ni][1]),
                          "+f"(acc[mi][ni][2]), "+f"(acc[mi][ni][3])
                        : "r"(a[mi][0]), "r"(a[mi][1]), "r"(a[mi][2]), "r"(a[mi][3]),
                          "r"(b[ni][0]), "r"(b[ni][1]));
        }
        __syncthreads();   // protects buffer reuse by issue of tile it+4
    }

    float* Pb = P + (long)blockIdx.y * N * 64;
#pragma unroll
    for (int mi = 0; mi < 2; mi++) {
        int r = m0 + warp_m * 32 + mi * 16 + g;
#pragma unroll
        for (int ni = 0; ni < 4; ni++) {
            int c = warp_n * 32 + ni * 8 + 2 * tq;
            *(float2*)(Pb + (long)r * 64 + c)       = make_float2(acc[mi][ni][0], acc[mi][ni][1]);
            *(float2*)(Pb + (long)(r + 8) * 64 + c) = make_float2(acc[mi][ni][2], acc[mi][ni][3]);
        }
    }
}

// ---------------- fused: combine split-K + relu + next-layer xW -> U -------
__global__ __launch_bounds__(256)
void scn_combine_xw(const float* __restrict__ P, const float* __restrict__ dinv,
                    const float* __restrict__ W, float* __restrict__ U, int N, int S) {
    __shared__ float Ws[64][64];
    __shared__ float Xs[32][64];
    int t = threadIdx.x;
    int r0 = blockIdx.x * 32;
#pragma unroll
    for (int j = 0; j < 4; j++)
        ((float4*)Ws)[t + 256 * j] = ((const float4*)W)[t + 256 * j];

    // combine: 32x64 tile = 512 float4, two per thread
    long stride4 = (long)N * 16;
#pragma unroll
    for (int j = 0; j < 2; j++) {
        int f = t + 256 * j;
        int lrow = f >> 4, c4 = f & 15;
        long base = (long)(r0 + lrow) * 16 + c4;
        float4 s = ((const float4*)P)[base];
        for (int q = 1; q < S; q++) {
            float4 v = ((const float4*)P)[(long)q * stride4 + base];
            s.x += v.x; s.y += v.y; s.z += v.z; s.w += v.w;
        }
        float d = dinv[r0 + lrow];
        *(float4*)&Xs[lrow][c4 * 4] = make_float4(
            fmaxf(d * s.x, 0.f), fmaxf(d * s.y, 0.f),
            fmaxf(d * s.z, 0.f), fmaxf(d * s.w, 0.f));
    }
    __syncthreads();

    int c = t & 63, g = t >> 6;
    float acc[8] = {0.f, 0.f, 0.f, 0.f, 0.f, 0.f, 0.f, 0.f};
#pragma unroll 16
    for (int k = 0; k < 64; k++) {
        float w = Ws[k][c];
#pragma unroll
        for (int r = 0; r < 8; r++)
            acc[r] = fmaf(Xs[g * 8 + r][k], w, acc[r]);
    }
#pragma unroll
    for (int r = 0; r < 8; r++) {
        int row = r0 + g * 8 + r;
        U[(long)row * 64 + c] = dinv[row] * acc[r];
    }
}

// ---------------- final combine (writes x for pooling) ----------------
__global__ void scn_combine_relu(const float4* __restrict__ P, const float* __restrict__ dinv,
                                 float4* __restrict__ X, int N, int S) {
    int idx = blockIdx.x * 256 + threadIdx.x;   // over N*16 float4
    int total4 = N * 16;
    if (idx >= total4) return;
    float4 s = P[idx];
    for (int q = 1; q < S; q++) {
        float4 v = P[(long)q * total4 + idx];
        s.x += v.x; s.y += v.y; s.z += v.z; s.w += v.w;
    }
    float d = dinv[idx >> 4];
    X[idx] = make_float4(fmaxf(d * s.x, 0.f), fmaxf(d * s.y, 0.f),
                         fmaxf(d * s.z, 0.f), fmaxf(d * s.w, 0.f));
}

// ---------------- deterministic segment pooling ----------------
__global__ void scn_pool_partial(const float* __restrict__ X, const int* __restrict__ bel,
                                 float* __restrict__ PP, int N) {
    __shared__ float part[2][BSEG][CCH];
    int t = threadIdx.x;                   // 128 threads
    int c = t & 63, s = t >> 6;
    for (int i = t; i < 2 * BSEG * CCH; i += 128) ((float*)part)[i] = 0.f;
    __syncthreads();
    int r0 = blockIdx.x * 256 + s * 128;
    for (int r = 0; r < 128; r++) {
        int row = r0 + r;
        int b = bel[row];
        part[s][b][c] += X[(long)row * 64 + c];
    }
    __syncthreads();
    float* out = PP + (long)blockIdx.x * BSEG * CCH;
    for (int i = t; i < BSEG * CCH; i += 128)
        out[i] = ((float*)part)[i] + ((float*)part)[BSEG * CCH + i];
}

__global__ void scn_pool_reduce(const float* __restrict__ PP, float* __restrict__ pooled, int G) {
    int idx = blockIdx.x * 256 + threadIdx.x;
    float s = 0.f;
    for (int g = 0; g < G; g++) s += PP[(long)g * BSEG * CCH + idx];
    pooled[idx] = s;
}

// ---------------- readout ----------------
__global__ void scn_readout(const float* __restrict__ pool,
                            const float* __restrict__ Wr0, const float* __restrict__ br0,
                            const float* __restrict__ Wr1, const float* __restrict__ br1,
                            const float* __restrict__ Wr2, const float* __restrict__ br2,
                            float* __restrict__ out) {
    int idx = blockIdx.x * 256 + threadIdx.x;
    if (idx >= BSEG * OUTC) return;
    int b = idx >> 5, o = idx & 31;
    float s = br0[o] + br1[o] + br2[o];
    const float* p0 = pool + 0 * BSEG * CCH + b * 64;
    const float* p1 = pool + 1 * BSEG * CCH + b * 64;
    const float* p2 = pool + 2 * BSEG * CCH + b * 64;
#pragma unroll 8
    for (int c = 0; c < 64; c++) {
        s = fmaf(p0[c], Wr0[c * 32 + o], s);
        s = fmaf(p1[c], Wr1[c * 32 + o], s);
        s = fmaf(p2[c], Wr2[c * 32 + o], s);
    }
    out[idx] = s;
}

// ---------------------------------------------------------------------------
static void* symAddr(const void* sym) {
    void* p = nullptr;
    cudaGetSymbolAddress(&p, sym);
    return p;
}

extern "C" void kernel_launch(void* const* d_in, const int* in_sizes, int n_in,
                              void* d_out, int out_size) {
    const float *x[3], *L[3], *W[3], *Wr[3], *br[3];
    const int* bel[3];

    if (in_sizes[0] == 16777216) {                       // alpha order
        for (int r = 0; r < 3; r++) {
            L[r]  = (const float*)d_in[0 + r];
            W[r]  = (const float*)d_in[3 + r];
            Wr[r] = (const float*)d_in[6 + r];
            bel[r]= (const int*)  d_in[9 + r];
            br[r] = (const float*)d_in[12 + r];
            x[r]  = (const float*)d_in[15 + r];
        }
    } else if (in_sizes[9] == 8192) {                    // dict order
        for (int r = 0; r < 3; r++) {
            x[r]  = (const float*)d_in[0 + r];
            L[r]  = (const float*)d_in[3 + r];
            bel[r]= (const int*)  d_in[6 + r];
            W[r]  = (const float*)d_in[9 + r];
        }
        Wr[0] = (const float*)d_in[12]; br[0] = (const float*)d_in[13];
        Wr[1] = (const float*)d_in[14]; br[1] = (const float*)d_in[15];
        Wr[2] = (const float*)d_in[16]; br[2] = (const float*)d_in[17];
    } else {                                             // signature order
        for (int r = 0; r < 3; r++) {
            x[r]  = (const float*)d_in[0 + r];
            L[r]  = (const float*)d_in[3 + r];
            W[r]  = (const float*)d_in[6 + r];
            bel[r]= (const int*)  d_in[15 + r];
        }
        Wr[0] = (const float*)d_in[9];  br[0] = (const float*)d_in[10];
        Wr[1] = (const float*)d_in[11]; br[1] = (const float*)d_in[12];
        Wr[2] = (const float*)d_in[13]; br[2] = (const float*)d_in[14];
    }

    int Ns[3];
    if (in_sizes[0] == 16777216) {
        Ns[0] = in_sizes[15] / 64; Ns[1] = in_sizes[16] / 64; Ns[2] = in_sizes[17] / 64;
    } else {
        Ns[0] = in_sizes[0] / 64;  Ns[1] = in_sizes[1] / 64;  Ns[2] = in_sizes[2] / 64;
    }

    float* dinvAll = (float*)symAddr(g_dinv);
    float* uAll    = (float*)symAddr(g_u);
    float* xAll    = (float*)symAddr(g_x);
    float* part    = (float*)symAddr(g_part);
    float* pp      = (float*)symAddr(g_pp);
    float* pool    = (float*)symAddr(g_pool);
    float* out     = (float*)d_out;

    cudaFuncSetAttribute(scn_gemm_tf32, cudaFuncAttributeMaxDynamicSharedMemorySize, GEMM_SMEM);

    // Fork three per-rank streams off the capture stream (stream 0).
    cudaStream_t st[3];
    cudaEvent_t root, ev[3];
    cudaEventCreateWithFlags(&root, cudaEventDisableTiming);
    cudaEventRecord(root, 0);
    for (int r = 0; r < 3; r++) {
        cudaStreamCreateWithFlags(&st[r], cudaStreamNonBlocking);
        cudaEventCreateWithFlags(&ev[r], cudaEventDisableTiming);
        cudaStreamWaitEvent(st[r], root, 0);
    }

    for (int r = 0; r < 3; r++) {
        int N = Ns[r];
        int S = (N >= 8192) ? 4 : 8;     // grid = (N/128)*S = 256 CTAs per GEMM
        int kChunk = N / S;
        float* dinv = dinvAll + r * NMAX;
        float* u    = uAll + (long)r * NMAX * CCH;
        float* xr   = xAll + (long)r * NMAX * CCH;
        float* pr   = part + (long)r * SPLIT_ELEMS;

        scn_rowsum<<<N, 256, 0, st[r]>>>(L[r], dinv, N);
        // layer 0
        scn_xw<<<N / 32, 256, 0, st[r]>>>(x[r], W[r], dinv, u, N);
        scn_gemm_tf32<<<dim3(N / 128, S), 256, GEMM_SMEM, st[r]>>>(L[r], u, pr, N, kChunk);
        // combine + relu + layer-1 xW fused
        scn_combine_xw<<<N / 32, 256, 0, st[r]>>>(pr, dinv, W[r] + 64 * 64, u, N, S);
        // layer 1
        scn_gemm_tf32<<<dim3(N / 128, S), 256, GEMM_SMEM, st[r]>>>(L[r], u, pr, N, kChunk);
        scn_combine_relu<<<N / 16, 256, 0, st[r]>>>((const float4*)pr, dinv, (float4*)xr, N, S);
        // pooling
        int G = N / 256;
        float* ppr = pp + (long)r * 32 * BSEG * CCH;
        scn_pool_partial<<<G, 128, 0, st[r]>>>(xr, bel[r], ppr, N);
        scn_pool_reduce<<<16, 256, 0, st[r]>>>(ppr, pool + r * BSEG * CCH, G);
        cudaEventRecord(ev[r], st[r]);
    }

    // Join back to the capture stream and run the readout there.
    for (int r = 0; r < 3; r++) cudaStreamWaitEvent((cudaStream_t)0, ev[r], 0);
    scn_readout<<<8, 256>>>(pool, Wr[0], br[0], Wr[1], br[1], Wr[2], br[2], out);

    for (int r = 0; r < 3; r++) {
        cudaStreamDestroy(st[r]);
        cudaEventDestroy(ev[r]);
    }
    cudaEventDestroy(root);
}

// round 9
// speedup vs baseline: 1.3317x; 1.3317x over previous
#include <cuda_runtime.h>
#include <cuda_bf16.h>

// ---------------------------------------------------------------------------
// SCN: per rank r with L (N x N), x (N x 64), W (2 x 64 x 64):
//   dinv_i = rsqrt(sum_j |L_ij|)  (0 if sum==0)
//   layer:  x = relu( dinv_i * sum_j L_ij * (dinv_j * (x @ W[layer])_j) )
//   pooled[b] = sum_{i: bel_i==b} x_i   (B=64);  out += pooled @ Wr + br
// Big GEMM on bf16 tensor cores (mma.m16n8k16). rowsum pass converts L->bf16
// once; xw kernels emit U transposed bf16 (k-contiguous for B fragments).
// 2-stage BK=64 cp.async pipeline, fused combine+xw, 3 per-rank streams.
// ---------------------------------------------------------------------------

#define NMAX   8192
#define CCH    64
#define BSEG   64
#define OUTC   32
#define SPLIT_ELEMS 2097152            // S*N*64: 4*8192*64 == 8*4096*64

__device__ float g_dinv[3 * NMAX];
__device__ float g_x[3][NMAX * CCH];
__device__ float g_part[3][SPLIT_ELEMS];
__device__ float g_pp[3 * 32 * BSEG * CCH];
__device__ float g_pool[3 * BSEG * CCH];
__device__ __align__(16) __nv_bfloat16 g_Lbf[100663296];   // 4096^2+8192^2+4096^2
__device__ __align__(16) __nv_bfloat16 g_ut[3][64 * NMAX]; // U transposed [c][j]

// ---------------- rowsum -> dinv, and L -> bf16 copy ----------------
__global__ void scn_rowsum(const float* __restrict__ L, float* __restrict__ dinv,
                           __nv_bfloat16* __restrict__ L16, int N) {
    int row = blockIdx.x;
    const float4* Lr = (const float4*)(L + (long)row * N);
    uint2* Wout = (uint2*)(L16 + (long)row * N);
    int n4 = N >> 2;
    float s = 0.f;
    for (int j = threadIdx.x; j < n4; j += blockDim.x) {
        float4 v = Lr[j];
        s += fabsf(v.x) + fabsf(v.y) + fabsf(v.z) + fabsf(v.w);
        __nv_bfloat162 p0 = __float22bfloat162_rn(make_float2(v.x, v.y));
        __nv_bfloat162 p1 = __float22bfloat162_rn(make_float2(v.z, v.w));
        Wout[j] = make_uint2(*(unsigned*)&p0, *(unsigned*)&p1);
    }
#pragma unroll
    for (int o = 16; o > 0; o >>= 1) s += __shfl_down_sync(0xffffffffu, s, o);
    __shared__ float red[8];
    int lane = threadIdx.x & 31, w = threadIdx.x >> 5;
    if (lane == 0) red[w] = s;
    __syncthreads();
    if (threadIdx.x < 8) {
        s = red[threadIdx.x];
#pragma unroll
        for (int o = 4; o > 0; o >>= 1) s += __shfl_down_sync(0xffu, s, o);
        if (threadIdx.x == 0) dinv[row] = (s > 0.f) ? rsqrtf(s) : 0.f;
    }
}

// pack two floats -> bf16x2 word (low = a, high = b)
__device__ __forceinline__ unsigned packbf(float a, float b) {
    __nv_bfloat162 p = __float22bfloat162_rn(make_float2(a, b));
    return *(unsigned*)&p;
}

// ---------------- Ut[c][j] = bf16( dinv_j * (x @ W)_jc )  (layer 0) --------
__global__ void scn_xw(const float* __restrict__ X, const float* __restrict__ W,
                       const float* __restrict__ dinv, __nv_bfloat16* __restrict__ Ut,
                       int N) {
    __shared__ float Ws[64][64];
    __shared__ float Xs[32][64];
    int t = threadIdx.x;
    int r0 = blockIdx.x * 32;
#pragma unroll
    for (int j = 0; j < 4; j++)
        ((float4*)Ws)[t + 256 * j] = ((const float4*)W)[t + 256 * j];
#pragma unroll
    for (int j = 0; j < 2; j++)
        ((float4*)Xs)[t + 256 * j] = ((const float4*)(X + (long)r0 * 64))[t + 256 * j];
    __syncthreads();
    int c = t & 63, g = t >> 6;
    float acc[8] = {0.f, 0.f, 0.f, 0.f, 0.f, 0.f, 0.f, 0.f};
#pragma unroll 16
    for (int k = 0; k < 64; k++) {
        float w = Ws[k][c];
#pragma unroll
        for (int r = 0; r < 8; r++)
            acc[r] = fmaf(Xs[g * 8 + r][k], w, acc[r]);
    }
    uint4 wv;
    unsigned* wp = (unsigned*)&wv;
#pragma unroll
    for (int p = 0; p < 4; p++) {
        int row = r0 + g * 8 + p * 2;
        wp[p] = packbf(dinv[row] * acc[p * 2], dinv[row + 1] * acc[p * 2 + 1]);
    }
    *(uint4*)(Ut + (long)c * N + r0 + g * 8) = wv;
}

// ---------------- bf16 tensor-core split-K GEMM, 2-stage BK=64 -------------
#define LS_B 18432        // 128 rows * 72 bf16 * 2B
#define US_B 9216         // 64 rows * 72 bf16 * 2B
#define ROWW 36           // 72 bf16 = 36 u32 words per row
#define GEMM_SMEM (2 * (LS_B + US_B))   // 55296

__device__ __forceinline__ void cpa16(unsigned smaddr, const void* g) {
    asm volatile("cp.async.cg.shared.global [%0], [%1], 16;" :: "r"(smaddr), "l"(g));
}

__global__ __launch_bounds__(256, 2)
void scn_gemm_bf16(const __nv_bfloat16* __restrict__ L, const __nv_bfloat16* __restrict__ Ut,
                   float* __restrict__ P, int N, int kChunk) {
    extern __shared__ char smem[];
    unsigned sbase = (unsigned)__cvta_generic_to_shared(smem);
    const unsigned* SW = (const unsigned*)smem;
    unsigned us_base = sbase + 2u * LS_B;

    int t = threadIdx.x;
    int wid = t >> 5, lane = t & 31;
    int g = lane >> 2, tq = lane & 3;
    int warp_m = wid & 3, warp_n = wid >> 2;          // 4 x 2 warp grid
    int m0 = blockIdx.x * 128;
    long kbase = (long)blockIdx.y * kChunk;
    int iters = kChunk / 64;

    // cp.async slots: L tile 128x64 bf16 = 1024 16B-chunks; U tile 64x64 = 512
    int l_row[4], l_ch[4], u_row[2], u_ch[2];
#pragma unroll
    for (int j = 0; j < 4; j++) { int f = t + 256 * j; l_row[j] = f >> 3; l_ch[j] = f & 7; }
#pragma unroll
    for (int j = 0; j < 2; j++) { int f = t + 256 * j; u_row[j] = f >> 3; u_ch[j] = f & 7; }

    float acc[2][4][4];
#pragma unroll
    for (int mi = 0; mi < 2; mi++)
#pragma unroll
        for (int ni = 0; ni < 4; ni++)
#pragma unroll
            for (int q = 0; q < 4; q++) acc[mi][ni][q] = 0.f;

#define ISSUE_TILE(IT, BUF)                                                            \
    do {                                                                               \
        long k0_ = kbase + (long)(IT) * 64;                                            \
        _Pragma("unroll")                                                              \
        for (int j = 0; j < 4; j++)                                                    \
            cpa16(sbase + (BUF) * LS_B + l_row[j] * 144 + l_ch[j] * 16,                \
                  L + (long)(m0 + l_row[j]) * N + k0_ + l_ch[j] * 8);                  \
        _Pragma("unroll")                                                              \
        for (int j = 0; j < 2; j++)                                                    \
            cpa16(us_base + (BUF) * US_B + u_row[j] * 144 + u_ch[j] * 16,              \
                  Ut + (long)u_row[j] * N + k0_ + u_ch[j] * 8);                        \
        asm volatile("cp.async.commit_group;");                                        \
    } while (0)

    ISSUE_TILE(0, 0);

    for (int it = 0; it < iters; it++) {
        int buf = it & 1;
        if (it + 1 < iters) {
            ISSUE_TILE(it + 1, buf ^ 1);
            asm volatile("cp.async.wait_group 1;");
        } else {
            asm volatile("cp.async.wait_group 0;");
        }
        __syncthreads();

        const unsigned* Lw = SW + (buf * LS_B) / 4;
        const unsigned* Uw = SW + (2 * LS_B + buf * US_B) / 4;
#pragma unroll
        for (int kk = 0; kk < 4; kk++) {           // 4 x k16 steps
            int kw = kk * 8 + tq;                  // word offset within row
            unsigned a[2][4], b[4][2];
#pragma unroll
            for (int mi = 0; mi < 2; mi++) {
                int r = warp_m * 32 + mi * 16 + g;
                a[mi][0] = Lw[r * ROWW + kw];
                a[mi][1] = Lw[(r + 8) * ROWW + kw];
                a[mi][2] = Lw[r * ROWW + kw + 4];
                a[mi][3] = Lw[(r + 8) * ROWW + kw + 4];
            }
#pragma unroll
            for (int ni = 0; ni < 4; ni++) {
                int n = warp_n * 32 + ni * 8 + g;
                b[ni][0] = Uw[n * ROWW + kw];
                b[ni][1] = Uw[n * ROWW + kw + 4];
            }
#pragma unroll
            for (int mi = 0; mi < 2; mi++)
#pragma unroll
                for (int ni = 0; ni < 4; ni++)
                    asm volatile(
                        "mma.sync.aligned.m16n8k16.row.col.f32.bf16.bf16.f32 "
                        "{%0,%1,%2,%3}, {%4,%5,%6,%7}, {%8,%9}, {%0,%1,%2,%3};"
                        : "+f"(acc[mi][ni][0]), "+f"(acc[mi][ni][1]),
                          "+f"(acc[mi][ni][2]), "+f"(acc[mi][ni][3])
                        : "r"(a[mi][0]), "r"(a[mi][1]), "r"(a[mi][2]), "r"(a[mi][3]),
                          "r"(b[ni][0]), "r"(b[ni][1]));
        }
        __syncthreads();
    }

    float* Pb = P + (long)blockIdx.y * N * 64;
#pragma unroll
    for (int mi = 0; mi < 2; mi++) {
        int r = m0 + warp_m * 32 + mi * 16 + g;
#pragma unroll
        for (int ni = 0; ni < 4; ni++) {
            int c = warp_n * 32 + ni * 8 + 2 * tq;
            *(float2*)(Pb + (long)r * 64 + c)       = make_float2(acc[mi][ni][0], acc[mi][ni][1]);
            *(float2*)(Pb + (long)(r + 8) * 64 + c) = make_float2(acc[mi][ni][2], acc[mi][ni][3]);
        }
    }
}

// ------- fused: combine split-K + relu + layer-1 xW -> transposed bf16 Ut --
__global__ __launch_bounds__(256)
void scn_combine_xw(const float* __restrict__ P, const float* __restrict__ dinv,
                    const float* __restrict__ W, __nv_bfloat16* __restrict__ Ut,
                    int N, int S) {
    __shared__ float Ws[64][64];
    __shared__ float Xs[32][64];
    int t = threadIdx.x;
    int r0 = blockIdx.x * 32;
#pragma unroll
    for (int j = 0; j < 4; j++)
        ((float4*)Ws)[t + 256 * j] = ((const float4*)W)[t + 256 * j];

    // combine: 32x64 tile = 512 float4, two per thread
    long stride4 = (long)N * 16;
#pragma unroll
    for (int j = 0; j < 2; j++) {
        int f = t + 256 * j;
        int lrow = f >> 4, c4 = f & 15;
        long base = (long)(r0 + lrow) * 16 + c4;
        float4 s = ((const float4*)P)[base];
        for (int q = 1; q < S; q++) {
            float4 v = ((const float4*)P)[(long)q * stride4 + base];
            s.x += v.x; s.y += v.y; s.z += v.z; s.w += v.w;
        }
        float d = dinv[r0 + lrow];
        *(float4*)&Xs[lrow][c4 * 4] = make_float4(
            fmaxf(d * s.x, 0.f), fmaxf(d * s.y, 0.f),
            fmaxf(d * s.z, 0.f), fmaxf(d * s.w, 0.f));
    }
    __syncthreads();

    int c = t & 63, g = t >> 6;
    float acc[8] = {0.f, 0.f, 0.f, 0.f, 0.f, 0.f, 0.f, 0.f};
#pragma unroll 16
    for (int k = 0; k < 64; k++) {
        float w = Ws[k][c];
#pragma unroll
        for (int r = 0; r < 8; r++)
            acc[r] = fmaf(Xs[g * 8 + r][k], w, acc[r]);
    }
    uint4 wv;
    unsigned* wp = (unsigned*)&wv;
#pragma unroll
    for (int p = 0; p < 4; p++) {
        int row = r0 + g * 8 + p * 2;
        wp[p] = packbf(dinv[row] * acc[p * 2], dinv[row + 1] * acc[p * 2 + 1]);
    }
    *(uint4*)(Ut + (long)c * N + r0 + g * 8) = wv;
}

// ---------------- final combine (writes fp32 x for pooling) ----------------
__global__ void scn_combine_relu(const float4* __restrict__ P, const float* __restrict__ dinv,
                                 float4* __restrict__ X, int N, int S) {
    int idx = blockIdx.x * 256 + threadIdx.x;   // over N*16 float4
    int total4 = N * 16;
    if (idx >= total4) return;
    float4 s = P[idx];
    for (int q = 1; q < S; q++) {
        float4 v = P[(long)q * total4 + idx];
        s.x += v.x; s.y += v.y; s.z += v.z; s.w += v.w;
    }
    float d = dinv[idx >> 4];
    X[idx] = make_float4(fmaxf(d * s.x, 0.f), fmaxf(d * s.y, 0.f),
                         fmaxf(d * s.z, 0.f), fmaxf(d * s.w, 0.f));
}

// ---------------- deterministic segment pooling ----------------
__global__ void scn_pool_partial(const float* __restrict__ X, const int* __restrict__ bel,
                                 float* __restrict__ PP, int N) {
    __shared__ float part[2][BSEG][CCH];
    int t = threadIdx.x;                   // 128 threads
    int c = t & 63, s = t >> 6;
    for (int i = t; i < 2 * BSEG * CCH; i += 128) ((float*)part)[i] = 0.f;
    __syncthreads();
    int r0 = blockIdx.x * 256 + s * 128;
    for (int r = 0; r < 128; r++) {
        int row = r0 + r;
        int b = bel[row];
        part[s][b][c] += X[(long)row * 64 + c];
    }
    __syncthreads();
    float* out = PP + (long)blockIdx.x * BSEG * CCH;
    for (int i = t; i < BSEG * CCH; i += 128)
        out[i] = ((float*)part)[i] + ((float*)part)[BSEG * CCH + i];
}

__global__ void scn_pool_reduce(const float* __restrict__ PP, float* __restrict__ pooled, int G) {
    int idx = blockIdx.x * 256 + threadIdx.x;
    float s = 0.f;
    for (int g = 0; g < G; g++) s += PP[(long)g * BSEG * CCH + idx];
    pooled[idx] = s;
}

// ---------------- readout ----------------
__global__ void scn_readout(const float* __restrict__ pool,
                            const float* __restrict__ Wr0, const float* __restrict__ br0,
                            const float* __restrict__ Wr1, const float* __restrict__ br1,
                            const float* __restrict__ Wr2, const float* __restrict__ br2,
                            float* __restrict__ out) {
    int idx = blockIdx.x * 256 + threadIdx.x;
    if (idx >= BSEG * OUTC) return;
    int b = idx >> 5, o = idx & 31;
    float s = br0[o] + br1[o] + br2[o];
    const float* p0 = pool + 0 * BSEG * CCH + b * 64;
    const float* p1 = pool + 1 * BSEG * CCH + b * 64;
    const float* p2 = pool + 2 * BSEG * CCH + b * 64;
#pragma unroll 8
    for (int c = 0; c < 64; c++) {
        s = fmaf(p0[c], Wr0[c * 32 + o], s);
        s = fmaf(p1[c], Wr1[c * 32 + o], s);
        s = fmaf(p2[c], Wr2[c * 32 + o], s);
    }
    out[idx] = s;
}

// ---------------------------------------------------------------------------
static void* symAddr(const void* sym) {
    void* p = nullptr;
    cudaGetSymbolAddress(&p, sym);
    return p;
}

extern "C" void kernel_launch(void* const* d_in, const int* in_sizes, int n_in,
                              void* d_out, int out_size) {
    const float *x[3], *L[3], *W[3], *Wr[3], *br[3];
    const int* bel[3];

    if (in_sizes[0] == 16777216) {                       // alpha order
        for (int r = 0; r < 3; r++) {
            L[r]  = (const float*)d_in[0 + r];
            W[r]  = (const float*)d_in[3 + r];
            Wr[r] = (const float*)d_in[6 + r];
            bel[r]= (const int*)  d_in[9 + r];
            br[r] = (const float*)d_in[12 + r];
            x[r]  = (const float*)d_in[15 + r];
        }
    } else if (in_sizes[9] == 8192) {                    // dict order
        for (int r = 0; r < 3; r++) {
            x[r]  = (const float*)d_in[0 + r];
            L[r]  = (const float*)d_in[3 + r];
            bel[r]= (const int*)  d_in[6 + r];
            W[r]  = (const float*)d_in[9 + r];
        }
        Wr[0] = (const float*)d_in[12]; br[0] = (const float*)d_in[13];
        Wr[1] = (const float*)d_in[14]; br[1] = (const float*)d_in[15];
        Wr[2] = (const float*)d_in[16]; br[2] = (const float*)d_in[17];
    } else {                                             // signature order
        for (int r = 0; r < 3; r++) {
            x[r]  = (const float*)d_in[0 + r];
            L[r]  = (const float*)d_in[3 + r];
            W[r]  = (const float*)d_in[6 + r];
            bel[r]= (const int*)  d_in[15 + r];
        }
        Wr[0] = (const float*)d_in[9];  br[0] = (const float*)d_in[10];
        Wr[1] = (const float*)d_in[11]; br[1] = (const float*)d_in[12];
        Wr[2] = (const float*)d_in[13]; br[2] = (const float*)d_in[14];
    }

    int Ns[3];
    if (in_sizes[0] == 16777216) {
        Ns[0] = in_sizes[15] / 64; Ns[1] = in_sizes[16] / 64; Ns[2] = in_sizes[17] / 64;
    } else {
        Ns[0] = in_sizes[0] / 64;  Ns[1] = in_sizes[1] / 64;  Ns[2] = in_sizes[2] / 64;
    }

    float* dinvAll = (float*)symAddr(g_dinv);
    float* xAll    = (float*)symAddr(g_x);
    float* part    = (float*)symAddr(g_part);
    float* pp      = (float*)symAddr(g_pp);
    float* pool    = (float*)symAddr(g_pool);
    __nv_bfloat16* LbfAll = (__nv_bfloat16*)symAddr(g_Lbf);
    __nv_bfloat16* utAll  = (__nv_bfloat16*)symAddr(g_ut);
    float* out     = (float*)d_out;

    long lbfOff[3];
    lbfOff[0] = 0;
    lbfOff[1] = lbfOff[0] + (long)Ns[0] * Ns[0];
    lbfOff[2] = lbfOff[1] + (long)Ns[1] * Ns[1];

    cudaFuncSetAttribute(scn_gemm_bf16, cudaFuncAttributeMaxDynamicSharedMemorySize, GEMM_SMEM);

    // Fork three per-rank streams off the capture stream (stream 0).
    cudaStream_t st[3];
    cudaEvent_t root, ev[3];
    cudaEventCreateWithFlags(&root, cudaEventDisableTiming);
    cudaEventRecord(root, 0);
    for (int r = 0; r < 3; r++) {
        cudaStreamCreateWithFlags(&st[r], cudaStreamNonBlocking);
        cudaEventCreateWithFlags(&ev[r], cudaEventDisableTiming);
        cudaStreamWaitEvent(st[r], root, 0);
    }

    for (int r = 0; r < 3; r++) {
        int N = Ns[r];
        int S = (N >= 8192) ? 4 : 8;     // grid = (N/128)*S = 256 CTAs per GEMM
        int kChunk = N / S;
        float* dinv = dinvAll + r * NMAX;
        __nv_bfloat16* Lbf = LbfAll + lbfOff[r];
        __nv_bfloat16* ut  = utAll + (long)r * 64 * NMAX;
        float* xr   = xAll + (long)r * NMAX * CCH;
        float* pr   = part + (long)r * SPLIT_ELEMS;

        scn_rowsum<<<N, 256, 0, st[r]>>>(L[r], dinv, Lbf, N);
        // layer 0
        scn_xw<<<N / 32, 256, 0, st[r]>>>(x[r], W[r], dinv, ut, N);
        scn_gemm_bf16<<<dim3(N / 128, S), 256, GEMM_SMEM, st[r]>>>(Lbf, ut, pr, N, kChunk);
        // combine + relu + layer-1 xW fused
        scn_combine_xw<<<N / 32, 256, 0, st[r]>>>(pr, dinv, W[r] + 64 * 64, ut, N, S);
        // layer 1
        scn_gemm_bf16<<<dim3(N / 128, S), 256, GEMM_SMEM, st[r]>>>(Lbf, ut, pr, N, kChunk);
        scn_combine_relu<<<N / 16, 256, 0, st[r]>>>((const float4*)pr, dinv, (float4*)xr, N, S);
        // pooling
        int G = N / 256;
        float* ppr = pp + (long)r * 32 * BSEG * CCH;
        scn_pool_partial<<<G, 128, 0, st[r]>>>(xr, bel[r], ppr, N);
        scn_pool_reduce<<<16, 256, 0, st[r]>>>(ppr, pool + r * BSEG * CCH, G);
        cudaEventRecord(ev[r], st[r]);
    }

    // Join back to the capture stream and run the readout there.
    for (int r = 0; r < 3; r++) cudaStreamWaitEvent((cudaStream_t)0, ev[r], 0);
    scn_readout<<<8, 256>>>(pool, Wr[0], br[0], Wr[1], br[1], Wr[2], br[2], out);

    for (int r = 0; r < 3; r++) {
        cudaStreamDestroy(st[r]);
        cudaEventDestroy(ev[r]);
    }
    cudaEventDestroy(root);
}

// round 10
// speedup vs baseline: 1.3754x; 1.0328x over previous
#include <cuda_runtime.h>
#include <cuda_bf16.h>

// ---------------------------------------------------------------------------
// SCN: per rank r with L (N x N), x (N x 64), W (2 x 64 x 64):
//   dinv_i = rsqrt(sum_j |L_ij|)  (0 if sum==0)
//   layer:  x = relu( dinv_i * sum_j L_ij * (dinv_j * (x @ W[layer])_j) )
//   pooled[b] = sum_{i: bel_i==b} x_i   (B=64);  out += pooled @ Wr + br
// Big GEMM on bf16 tensor cores (m16n8k16); rowsum converts L->bf16 once;
// U kept transposed bf16. 3-stage BK=64 cp.async GEMM, combine kernels
// templated on split-K S, final combine fused into pooling. 3 streams.
// ---------------------------------------------------------------------------

#define NMAX   8192
#define CCH    64
#define BSEG   64
#define OUTC   32
#define SPLIT_ELEMS 2097152            // S*N*64: 4*8192*64 == 8*4096*64

__device__ float g_dinv[3 * NMAX];
__device__ float g_part[3][SPLIT_ELEMS];
__device__ float g_pp[3 * 32 * BSEG * CCH];
__device__ float g_pool[3 * BSEG * CCH];
__device__ __align__(16) __nv_bfloat16 g_Lbf[100663296];   // 4096^2+8192^2+4096^2
__device__ __align__(16) __nv_bfloat16 g_ut[3][64 * NMAX]; // U transposed [c][j]

// ---------------- rowsum -> dinv, and L -> bf16 copy ----------------
__global__ void scn_rowsum(const float* __restrict__ L, float* __restrict__ dinv,
                           __nv_bfloat16* __restrict__ L16, int N) {
    int row = blockIdx.x;
    const float4* Lr = (const float4*)(L + (long)row * N);
    uint2* Wout = (uint2*)(L16 + (long)row * N);
    int n4 = N >> 2;
    float s = 0.f;
    for (int j = threadIdx.x; j < n4; j += blockDim.x) {
        float4 v = Lr[j];
        s += fabsf(v.x) + fabsf(v.y) + fabsf(v.z) + fabsf(v.w);
        __nv_bfloat162 p0 = __float22bfloat162_rn(make_float2(v.x, v.y));
        __nv_bfloat162 p1 = __float22bfloat162_rn(make_float2(v.z, v.w));
        Wout[j] = make_uint2(*(unsigned*)&p0, *(unsigned*)&p1);
    }
#pragma unroll
    for (int o = 16; o > 0; o >>= 1) s += __shfl_down_sync(0xffffffffu, s, o);
    __shared__ float red[8];
    int lane = threadIdx.x & 31, w = threadIdx.x >> 5;
    if (lane == 0) red[w] = s;
    __syncthreads();
    if (threadIdx.x < 8) {
        s = red[threadIdx.x];
#pragma unroll
        for (int o = 4; o > 0; o >>= 1) s += __shfl_down_sync(0xffu, s, o);
        if (threadIdx.x == 0) dinv[row] = (s > 0.f) ? rsqrtf(s) : 0.f;
    }
}

__device__ __forceinline__ unsigned packbf(float a, float b) {
    __nv_bfloat162 p = __float22bfloat162_rn(make_float2(a, b));
    return *(unsigned*)&p;
}

// ---------------- Ut[c][j] = bf16( dinv_j * (x @ W)_jc )  (layer 0) --------
__global__ void scn_xw(const float* __restrict__ X, const float* __restrict__ W,
                       const float* __restrict__ dinv, __nv_bfloat16* __restrict__ Ut,
                       int N) {
    __shared__ float Ws[64][64];
    __shared__ float Xs[32][64];
    int t = threadIdx.x;
    int r0 = blockIdx.x * 32;
#pragma unroll
    for (int j = 0; j < 4; j++)
        ((float4*)Ws)[t + 256 * j] = ((const float4*)W)[t + 256 * j];
#pragma unroll
    for (int j = 0; j < 2; j++)
        ((float4*)Xs)[t + 256 * j] = ((const float4*)(X + (long)r0 * 64))[t + 256 * j];
    __syncthreads();
    int c = t & 63, g = t >> 6;
    float acc[8] = {0.f, 0.f, 0.f, 0.f, 0.f, 0.f, 0.f, 0.f};
#pragma unroll 16
    for (int k = 0; k < 64; k++) {
        float w = Ws[k][c];
#pragma unroll
        for (int r = 0; r < 8; r++)
            acc[r] = fmaf(Xs[g * 8 + r][k], w, acc[r]);
    }
    uint4 wv;
    unsigned* wp = (unsigned*)&wv;
#pragma unroll
    for (int p = 0; p < 4; p++) {
        int row = r0 + g * 8 + p * 2;
        wp[p] = packbf(dinv[row] * acc[p * 2], dinv[row + 1] * acc[p * 2 + 1]);
    }
    *(uint4*)(Ut + (long)c * N + r0 + g * 8) = wv;
}

// ---------------- bf16 tensor-core split-K GEMM, 3-stage BK=64 -------------
#define LS_B 18432        // 128 rows * 72 bf16 * 2B
#define US_B 9216         // 64 rows * 72 bf16 * 2B
#define ROWW 36           // 72 bf16 = 36 u32 words per row
#define GSTAGES 3
#define GEMM_SMEM (GSTAGES * (LS_B + US_B))   // 82944

__device__ __forceinline__ void cpa16(unsigned smaddr, const void* g) {
    asm volatile("cp.async.cg.shared.global [%0], [%1], 16;" :: "r"(smaddr), "l"(g));
}

__global__ __launch_bounds__(256, 2)
void scn_gemm_bf16(const __nv_bfloat16* __restrict__ L, const __nv_bfloat16* __restrict__ Ut,
                   float* __restrict__ P, int N, int kChunk) {
    extern __shared__ char smem[];
    unsigned sbase = (unsigned)__cvta_generic_to_shared(smem);
    const unsigned* SW = (const unsigned*)smem;
    unsigned us_base = sbase + (unsigned)GSTAGES * LS_B;

    int t = threadIdx.x;
    int wid = t >> 5, lane = t & 31;
    int g = lane >> 2, tq = lane & 3;
    int warp_m = wid & 3, warp_n = wid >> 2;          // 4 x 2 warp grid
    int m0 = blockIdx.x * 128;
    long kbase = (long)blockIdx.y * kChunk;
    int iters = kChunk / 64;

    int l_row[4], l_ch[4], u_row[2], u_ch[2];
#pragma unroll
    for (int j = 0; j < 4; j++) { int f = t + 256 * j; l_row[j] = f >> 3; l_ch[j] = f & 7; }
#pragma unroll
    for (int j = 0; j < 2; j++) { int f = t + 256 * j; u_row[j] = f >> 3; u_ch[j] = f & 7; }

    float acc[2][4][4];
#pragma unroll
    for (int mi = 0; mi < 2; mi++)
#pragma unroll
        for (int ni = 0; ni < 4; ni++)
#pragma unroll
            for (int q = 0; q < 4; q++) acc[mi][ni][q] = 0.f;

#define ISSUE_TILE(IT, BUF)                                                            \
    do {                                                                               \
        long k0_ = kbase + (long)(IT) * 64;                                            \
        _Pragma("unroll")                                                              \
        for (int j = 0; j < 4; j++)                                                    \
            cpa16(sbase + (BUF) * LS_B + l_row[j] * 144 + l_ch[j] * 16,                \
                  L + (long)(m0 + l_row[j]) * N + k0_ + l_ch[j] * 8);                  \
        _Pragma("unroll")                                                              \
        for (int j = 0; j < 2; j++)                                                    \
            cpa16(us_base + (BUF) * US_B + u_row[j] * 144 + u_ch[j] * 16,              \
                  Ut + (long)u_row[j] * N + k0_ + u_ch[j] * 8);                        \
        asm volatile("cp.async.commit_group;");                                        \
    } while (0)

    ISSUE_TILE(0, 0);
    ISSUE_TILE(1, 1);

    int buf = 0;
    for (int it = 0; it < iters; it++) {
        if (it + 2 < iters) {
            int nb = buf + 2; if (nb >= GSTAGES) nb -= GSTAGES;
            ISSUE_TILE(it + 2, nb);
            asm volatile("cp.async.wait_group 2;");
        } else {
            if (it + 2 == iters + 0 && it + 1 < iters)
                asm volatile("cp.async.wait_group 1;");
            else
                asm volatile("cp.async.wait_group 0;");
        }
        __syncthreads();

        const unsigned* Lw = SW + (buf * LS_B) / 4;
        const unsigned* Uw = SW + (GSTAGES * LS_B + buf * US_B) / 4;
#pragma unroll
        for (int kk = 0; kk < 4; kk++) {           // 4 x k16 steps
            int kw = kk * 8 + tq;
            unsigned a[2][4], b[4][2];
#pragma unroll
            for (int mi = 0; mi < 2; mi++) {
                int r = warp_m * 32 + mi * 16 + g;
                a[mi][0] = Lw[r * ROWW + kw];
                a[mi][1] = Lw[(r + 8) * ROWW + kw];
                a[mi][2] = Lw[r * ROWW + kw + 4];
                a[mi][3] = Lw[(r + 8) * ROWW + kw + 4];
            }
#pragma unroll
            for (int ni = 0; ni < 4; ni++) {
                int n = warp_n * 32 + ni * 8 + g;
                b[ni][0] = Uw[n * ROWW + kw];
                b[ni][1] = Uw[n * ROWW + kw + 4];
            }
#pragma unroll
            for (int mi = 0; mi < 2; mi++)
#pragma unroll
                for (int ni = 0; ni < 4; ni++)
                    asm volatile(
                        "mma.sync.aligned.m16n8k16.row.col.f32.bf16.bf16.f32 "
                        "{%0,%1,%2,%3}, {%4,%5,%6,%7}, {%8,%9}, {%0,%1,%2,%3};"
                        : "+f"(acc[mi][ni][0]), "+f"(acc[mi][ni][1]),
                          "+f"(acc[mi][ni][2]), "+f"(acc[mi][ni][3])
                        : "r"(a[mi][0]), "r"(a[mi][1]), "r"(a[mi][2]), "r"(a[mi][3]),
                          "r"(b[ni][0]), "r"(b[ni][1]));
        }
        __syncthreads();
        if (++buf == GSTAGES) buf = 0;
    }

    float* Pb = P + (long)blockIdx.y * N * 64;
#pragma unroll
    for (int mi = 0; mi < 2; mi++) {
        int r = m0 + warp_m * 32 + mi * 16 + g;
#pragma unroll
        for (int ni = 0; ni < 4; ni++) {
            int c = warp_n * 32 + ni * 8 + 2 * tq;
            *(float2*)(Pb + (long)r * 64 + c)       = make_float2(acc[mi][ni][0], acc[mi][ni][1]);
            *(float2*)(Pb + (long)(r + 8) * 64 + c) = make_float2(acc[mi][ni][2], acc[mi][ni][3]);
        }
    }
}

// ------- fused: combine split-K + relu + layer-1 xW -> transposed bf16 Ut --
template <int S>
__global__ __launch_bounds__(256)
void scn_combine_xw(const float* __restrict__ P, const float* __restrict__ dinv,
                    const float* __restrict__ W, __nv_bfloat16* __restrict__ Ut, int N) {
    __shared__ float Ws[64][64];
    __shared__ float Xs[32][64];
    int t = threadIdx.x;
    int r0 = blockIdx.x * 32;
#pragma unroll
    for (int j = 0; j < 4; j++)
        ((float4*)Ws)[t + 256 * j] = ((const float4*)W)[t + 256 * j];

    long stride4 = (long)N * 16;
#pragma unroll
    for (int j = 0; j < 2; j++) {
        int f = t + 256 * j;
        int lrow = f >> 4, c4 = f & 15;
        long base = (long)(r0 + lrow) * 16 + c4;
        float4 s = ((const float4*)P)[base];
#pragma unroll
        for (int q = 1; q < S; q++) {
            float4 v = ((const float4*)P)[(long)q * stride4 + base];
            s.x += v.x; s.y += v.y; s.z += v.z; s.w += v.w;
        }
        float d = dinv[r0 + lrow];
        *(float4*)&Xs[lrow][c4 * 4] = make_float4(
            fmaxf(d * s.x, 0.f), fmaxf(d * s.y, 0.f),
            fmaxf(d * s.z, 0.f), fmaxf(d * s.w, 0.f));
    }
    __syncthreads();

    int c = t & 63, g = t >> 6;
    float acc[8] = {0.f, 0.f, 0.f, 0.f, 0.f, 0.f, 0.f, 0.f};
#pragma unroll 16
    for (int k = 0; k < 64; k++) {
        float w = Ws[k][c];
#pragma unroll
        for (int r = 0; r < 8; r++)
            acc[r] = fmaf(Xs[g * 8 + r][k], w, acc[r]);
    }
    uint4 wv;
    unsigned* wp = (unsigned*)&wv;
#pragma unroll
    for (int p = 0; p < 4; p++) {
        int row = r0 + g * 8 + p * 2;
        wp[p] = packbf(dinv[row] * acc[p * 2], dinv[row + 1] * acc[p * 2 + 1]);
    }
    *(uint4*)(Ut + (long)c * N + r0 + g * 8) = wv;
}

// ------- fused: final combine + relu + deterministic segment pooling -------
// grid = N/256, 256 threads = 4 subgroups x 64 columns, 64KB dynamic smem.
template <int S>
__global__ __launch_bounds__(256)
void scn_combine_pool(const float* __restrict__ P, const float* __restrict__ dinv,
                      const int* __restrict__ bel, float* __restrict__ PP, int N) {
    extern __shared__ float part[];              // [4][64][64]
    int t = threadIdx.x;
    int c = t & 63, sg = t >> 6;                 // subgroup 0..3
    for (int i = t; i < 4 * BSEG * CCH; i += 256) part[i] = 0.f;
    __syncthreads();
    float* my = part + sg * BSEG * CCH;
    long stride = (long)N * 64;
    int r0 = blockIdx.x * 256 + sg * 64;
    for (int i = 0; i < 64; i++) {               // fixed order -> deterministic
        int row = r0 + i;
        long base = (long)row * 64 + c;
        float s = P[base];
#pragma unroll
        for (int q = 1; q < S; q++) s += P[(long)q * stride + base];
        float v = fmaxf(dinv[row] * s, 0.f);
        my[bel[row] * CCH + c] += v;
    }
    __syncthreads();
    float* out = PP + (long)blockIdx.x * BSEG * CCH;
    for (int i = t; i < BSEG * CCH; i += 256)
        out[i] = ((part[i] + part[BSEG * CCH + i]) +
                  (part[2 * BSEG * CCH + i] + part[3 * BSEG * CCH + i]));
}

__global__ void scn_pool_reduce(const float* __restrict__ PP, float* __restrict__ pooled, int G) {
    int idx = blockIdx.x * 256 + threadIdx.x;
    float s = 0.f;
    for (int g = 0; g < G; g++) s += PP[(long)g * BSEG * CCH + idx];
    pooled[idx] = s;
}

// ---------------- readout ----------------
__global__ void scn_readout(const float* __restrict__ pool,
                            const float* __restrict__ Wr0, const float* __restrict__ br0,
                            const float* __restrict__ Wr1, const float* __restrict__ br1,
                            const float* __restrict__ Wr2, const float* __restrict__ br2,
                            float* __restrict__ out) {
    int idx = blockIdx.x * 256 + threadIdx.x;
    if (idx >= BSEG * OUTC) return;
    int b = idx >> 5, o = idx & 31;
    float s = br0[o] + br1[o] + br2[o];
    const float* p0 = pool + 0 * BSEG * CCH + b * 64;
    const float* p1 = pool + 1 * BSEG * CCH + b * 64;
    const float* p2 = pool + 2 * BSEG * CCH + b * 64;
#pragma unroll 8
    for (int c = 0; c < 64; c++) {
        s = fmaf(p0[c], Wr0[c * 32 + o], s);
        s = fmaf(p1[c], Wr1[c * 32 + o], s);
        s = fmaf(p2[c], Wr2[c * 32 + o], s);
    }
    out[idx] = s;
}

// ---------------------------------------------------------------------------
static void* symAddr(const void* sym) {
    void* p = nullptr;
    cudaGetSymbolAddress(&p, sym);
    return p;
}

extern "C" void kernel_launch(void* const* d_in, const int* in_sizes, int n_in,
                              void* d_out, int out_size) {
    const float *x[3], *L[3], *W[3], *Wr[3], *br[3];
    const int* bel[3];

    if (in_sizes[0] == 16777216) {                       // alpha order
        for (int r = 0; r < 3; r++) {
            L[r]  = (const float*)d_in[0 + r];
            W[r]  = (const float*)d_in[3 + r];
            Wr[r] = (const float*)d_in[6 + r];
            bel[r]= (const int*)  d_in[9 + r];
            br[r] = (const float*)d_in[12 + r];
            x[r]  = (const float*)d_in[15 + r];
        }
    } else if (in_sizes[9] == 8192) {                    // dict order
        for (int r = 0; r < 3; r++) {
            x[r]  = (const float*)d_in[0 + r];
            L[r]  = (const float*)d_in[3 + r];
            bel[r]= (const int*)  d_in[6 + r];
            W[r]  = (const float*)d_in[9 + r];
        }
        Wr[0] = (const float*)d_in[12]; br[0] = (const float*)d_in[13];
        Wr[1] = (const float*)d_in[14]; br[1] = (const float*)d_in[15];
        Wr[2] = (const float*)d_in[16]; br[2] = (const float*)d_in[17];
    } else {                                             // signature order
        for (int r = 0; r < 3; r++) {
            x[r]  = (const float*)d_in[0 + r];
            L[r]  = (const float*)d_in[3 + r];
            W[r]  = (const float*)d_in[6 + r];
            bel[r]= (const int*)  d_in[15 + r];
        }
        Wr[0] = (const float*)d_in[9];  br[0] = (const float*)d_in[10];
        Wr[1] = (const float*)d_in[11]; br[1] = (const float*)d_in[12];
        Wr[2] = (const float*)d_in[13]; br[2] = (const float*)d_in[14];
    }

    int Ns[3];
    if (in_sizes[0] == 16777216) {
        Ns[0] = in_sizes[15] / 64; Ns[1] = in_sizes[16] / 64; Ns[2] = in_sizes[17] / 64;
    } else {
        Ns[0] = in_sizes[0] / 64;  Ns[1] = in_sizes[1] / 64;  Ns[2] = in_sizes[2] / 64;
    }

    float* dinvAll = (float*)symAddr(g_dinv);
    float* part    = (float*)symAddr(g_part);
    float* pp      = (float*)symAddr(g_pp);
    float* pool    = (float*)symAddr(g_pool);
    __nv_bfloat16* LbfAll = (__nv_bfloat16*)symAddr(g_Lbf);
    __nv_bfloat16* utAll  = (__nv_bfloat16*)symAddr(g_ut);
    float* out     = (float*)d_out;

    long lbfOff[3];
    lbfOff[0] = 0;
    lbfOff[1] = lbfOff[0] + (long)Ns[0] * Ns[0];
    lbfOff[2] = lbfOff[1] + (long)Ns[1] * Ns[1];

    cudaFuncSetAttribute(scn_gemm_bf16, cudaFuncAttributeMaxDynamicSharedMemorySize, GEMM_SMEM);
    cudaFuncSetAttribute(scn_combine_pool<4>, cudaFuncAttributeMaxDynamicSharedMemorySize, 65536);
    cudaFuncSetAttribute(scn_combine_pool<8>, cudaFuncAttributeMaxDynamicSharedMemorySize, 65536);

    // Fork three per-rank streams off the capture stream (stream 0).
    cudaStream_t st[3];
    cudaEvent_t root, ev[3];
    cudaEventCreateWithFlags(&root, cudaEventDisableTiming);
    cudaEventRecord(root, 0);
    for (int r = 0; r < 3; r++) {
        cudaStreamCreateWithFlags(&st[r], cudaStreamNonBlocking);
        cudaEventCreateWithFlags(&ev[r], cudaEventDisableTiming);
        cudaStreamWaitEvent(st[r], root, 0);
    }

    for (int r = 0; r < 3; r++) {
        int N = Ns[r];
        int S = (N >= 8192) ? 4 : 8;     // grid = (N/128)*S = 256 CTAs per GEMM
        int kChunk = N / S;
        float* dinv = dinvAll + r * NMAX;
        __nv_bfloat16* Lbf = LbfAll + lbfOff[r];
        __nv_bfloat16* ut  = utAll + (long)r * 64 * NMAX;
        float* pr   = part + (long)r * SPLIT_ELEMS;

        scn_rowsum<<<N, 256, 0, st[r]>>>(L[r], dinv, Lbf, N);
        // layer 0
        scn_xw<<<N / 32, 256, 0, st[r]>>>(x[r], W[r], dinv, ut, N);
        scn_gemm_bf16<<<dim3(N / 128, S), 256, GEMM_SMEM, st[r]>>>(Lbf, ut, pr, N, kChunk);
        // combine + relu + layer-1 xW fused
        if (S == 4)
            scn_combine_xw<4><<<N / 32, 256, 0, st[r]>>>(pr, dinv, W[r] + 64 * 64, ut, N);
        else
            scn_combine_xw<8><<<N / 32, 256, 0, st[r]>>>(pr, dinv, W[r] + 64 * 64, ut, N);
        // layer 1
        scn_gemm_bf16<<<dim3(N / 128, S), 256, GEMM_SMEM, st[r]>>>(Lbf, ut, pr, N, kChunk);
        // final combine + relu + pooling fused
        int G = N / 256;
        float* ppr = pp + (long)r * 32 * BSEG * CCH;
        if (S == 4)
            scn_combine_pool<4><<<G, 256, 65536, st[r]>>>(pr, dinv, bel[r], ppr, N);
        else
            scn_combine_pool<8><<<G, 256, 65536, st[r]>>>(pr, dinv, bel[r], ppr, N);
        scn_pool_reduce<<<16, 256, 0, st[r]>>>(ppr, pool + r * BSEG * CCH, G);
        cudaEventRecord(ev[r], st[r]);
    }

    // Join back to the capture stream and run the readout there.
    for (int r = 0; r < 3; r++) cudaStreamWaitEvent((cudaStream_t)0, ev[r], 0);
    scn_readout<<<8, 256>>>(pool, Wr[0], br[0], Wr[1], br[1], Wr[2], br[2], out);

    for (int r = 0; r < 3; r++) {
        cudaStreamDestroy(st[r]);
        cudaEventDestroy(ev[r]);
    }
    cudaEventDestroy(root);
}